// round 16
// baseline (speedup 1.0000x reference)
#include <cuda_runtime.h>
#include <cuda_fp16.h>
#include <math.h>
#include <stdint.h>

#define S_DIM 128
#define R_DIM 256
#define C_DIM 256
#define H_DIM 8
#define D_DIM 32
#define HD_DIM 256
#define SR_DIM (S_DIM * R_DIM)

#define LOG2E 1.4426950408889634f

// Scratch (device globals; allocation-free contract)
__device__ float  g_biasT[H_DIM * R_DIM * R_DIM];        // [h][q][k], pre-scaled by log2e
__device__ __half g_qh[SR_DIM * 256];                    // q input, half
__device__ __half g_kvh[SR_DIM * 256];                   // kv input, half
__device__ __half g_Qh[S_DIM * H_DIM * R_DIM * D_DIM];   // [s][h][r][d], pre-scaled norm*log2e
__device__ __half g_Kh[S_DIM * H_DIM * R_DIM * D_DIM];
__device__ __half g_Vh[S_DIM * H_DIM * R_DIM * D_DIM];
__device__ __half g_Gh[S_DIM * H_DIM * R_DIM * D_DIM];
__device__ __half g_Oh[S_DIM * H_DIM * R_DIM * D_DIM];   // gated O
__device__ __half g_WTh[5 * 256 * 256];                  // weights [n][k], half

// ---------------------------------------------------------------------------
// helpers
// ---------------------------------------------------------------------------
__device__ __forceinline__ void mma_f16(float c[4],
                                        uint32_t a0, uint32_t a1,
                                        uint32_t a2, uint32_t a3,
                                        uint32_t b0, uint32_t b1) {
    asm volatile(
        "mma.sync.aligned.m16n8k16.row.col.f32.f16.f16.f32 "
        "{%0,%1,%2,%3}, {%4,%5,%6,%7}, {%8,%9}, {%0,%1,%2,%3};"
        : "+f"(c[0]), "+f"(c[1]), "+f"(c[2]), "+f"(c[3])
        : "r"(a0), "r"(a1), "r"(a2), "r"(a3), "r"(b0), "r"(b1));
}

__device__ __forceinline__ void ldsm_x4(uint32_t& r0, uint32_t& r1,
                                        uint32_t& r2, uint32_t& r3,
                                        uint32_t addr) {
    asm volatile("ldmatrix.sync.aligned.m8n8.x4.shared.b16 {%0,%1,%2,%3}, [%4];"
                 : "=r"(r0), "=r"(r1), "=r"(r2), "=r"(r3) : "r"(addr));
}

__device__ __forceinline__ void cp16(uint32_t smem_addr, const void* gptr) {
    asm volatile("cp.async.cg.shared.global [%0], [%1], 16;"
                 :: "r"(smem_addr), "l"(gptr));
}
__device__ __forceinline__ void cp_commit() {
    asm volatile("cp.async.commit_group;");
}
template <int N>
__device__ __forceinline__ void cp_wait() {
    asm volatile("cp.async.wait_group %0;" :: "n"(N));
}

// fp16 GEMM tiling (unchanged from R15): block 128x128, BK=64, 8 warps of
// 64x32, ldmatrix frag loads, 2-stage pipeline, 2 CTAs/SM.
#define ROWW 36
#define A_CH_WORDS (128 * ROWW)
#define B_CH_WORDS (128 * ROWW)
#define GEMM_SMEM_BYTES (2 * (A_CH_WORDS + B_CH_WORDS) * 4)  // 73728

// ---------------------------------------------------------------------------
// Kernel 1: bias [q][k][h] -> biasT [h][q][k], scaled by log2e.
// ---------------------------------------------------------------------------
__global__ void bias_transpose_kernel(const float* __restrict__ bias) {
    int idx = blockIdx.x * blockDim.x + threadIdx.x;
    if (idx < H_DIM * R_DIM * R_DIM) {
        int k  = idx & 255;
        int qq = (idx >> 8) & 255;
        int h  = idx >> 16;
        g_biasT[idx] = bias[((qq << 8) + k) * 8 + h] * LOG2E;
    }
}

// ---------------------------------------------------------------------------
// Kernel 1b: fp32 -> fp16 conversion of the two activation inputs.
// ---------------------------------------------------------------------------
__global__ void f2h_kernel(const float* __restrict__ qin,
                           const float* __restrict__ kvin) {
    const float* src = blockIdx.y ? kvin : qin;
    __half* dst = blockIdx.y ? g_kvh : g_qh;
    int i = blockIdx.x * 256 + threadIdx.x;     // float4 index
    float4 v = ((const float4*)src)[i];
    __half2* d = (__half2*)(dst + i * 4);
    d[0] = __floats2half2_rn(v.x, v.y);
    d[1] = __floats2half2_rn(v.z, v.w);
}

// ---------------------------------------------------------------------------
// Kernel 1c: transpose five 256x256 weight matrices to K-major [n][k], half.
// ---------------------------------------------------------------------------
__global__ void wt_transpose_kernel(const float* __restrict__ w_q,
                                    const float* __restrict__ w_k,
                                    const float* __restrict__ w_v,
                                    const float* __restrict__ w_g,
                                    const float* __restrict__ w_o) {
    __shared__ float tile[32][33];
    int which = blockIdx.z;
    const float* W = (which == 0) ? w_q : (which == 1) ? w_k
                   : (which == 2) ? w_v : (which == 3) ? w_g : w_o;
    __half* Out = g_WTh + which * 65536;
    int bx = blockIdx.x * 32, by = blockIdx.y * 32;
    int tx = threadIdx.x, ty = threadIdx.y;   // 32 x 8
#pragma unroll
    for (int i = 0; i < 32; i += 8)
        tile[ty + i][tx] = W[(by + ty + i) * 256 + bx + tx];
    __syncthreads();
#pragma unroll
    for (int i = 0; i < 32; i += 8)
        Out[(bx + ty + i) * 256 + by + tx] = __float2half_rn(tile[tx][ty + i]);
}

// ---------------------------------------------------------------------------
// Kernel 2: fp16 m16n8k16 GEMM with ldmatrix fragment loads (as R15).
// type 0: Q (scaled norm*log2e), 1: K, 2: V, 3: G (sigmoid), 4: outproj.
// ---------------------------------------------------------------------------
__global__ void __launch_bounds__(256, 2)
hgemm_kernel(const float* __restrict__ b_g,
             const float* __restrict__ b_o,
             float* __restrict__ out,
             int type_base) {
    extern __shared__ uint32_t smem[];
    uint32_t* Asm = smem;
    uint32_t* Bsm = smem + 2 * A_CH_WORDS;

    int type = blockIdx.z + type_base;
    const __half* Ah = (type == 1 || type == 2) ? g_kvh
                     : (type == 4) ? g_Oh : g_qh;
    const __half* Bh = g_WTh + type * 65536;

    int t = threadIdx.x, lane = t & 31, w = t >> 5;
    int warpM = w >> 2, warpN = w & 3;
    int bM = blockIdx.x * 128;
    int bN = blockIdx.y * 128;
    int gid = lane >> 2, tid = lane & 3;

    uint32_t asBase = (uint32_t)__cvta_generic_to_shared(Asm);
    uint32_t bsBase = (uint32_t)__cvta_generic_to_shared(Bsm);

    int a_row = warpM * 64 + (lane & 7) + ((lane >> 3) & 1) * 8;
    int a_colw = (lane >> 4) * 4;
    int b_row = warpN * 32 + (lane & 7) + (lane >> 4) * 8;
    int b_colw = ((lane >> 3) & 1) * 4;
    uint32_t aAddr0 = asBase + (a_row * ROWW + a_colw) * 4;
    uint32_t bAddr0 = bsBase + (b_row * ROWW + b_colw) * 4;

    auto issue = [&](int kt, int buf) {
        int kc = kt * 64;
#pragma unroll
        for (int p = 0; p < 4; p++) {
            int idx = t + p * 256;
            int r = idx >> 3, c4 = idx & 7;
            const __half* src;
            if (type == 4) {
                int m = bM + r;
                int s = m >> 8, rr = m & 255;
                int head = (kc >> 5) + (c4 >> 2);
                int d0 = (c4 & 3) * 8;
                src = g_Oh + ((s * 8 + head) * 256 + rr) * 32 + d0;
            } else {
                src = Ah + (bM + r) * 256 + kc + c4 * 8;
            }
            cp16(asBase + (buf * A_CH_WORDS + r * ROWW + c4 * 4) * 4, src);
        }
#pragma unroll
        for (int p = 0; p < 4; p++) {
            int idx = t + p * 256;
            int r = idx >> 3, c4 = idx & 7;
            cp16(bsBase + (buf * B_CH_WORDS + r * ROWW + c4 * 4) * 4,
                 Bh + (bN + r) * 256 + kc + c4 * 8);
        }
        cp_commit();
    };

    float acc[4][4][4];
#pragma unroll
    for (int i = 0; i < 4; i++)
#pragma unroll
        for (int j = 0; j < 4; j++)
#pragma unroll
            for (int r = 0; r < 4; r++) acc[i][j][r] = 0.f;

    issue(0, 0);

    for (int kt = 0; kt < 4; kt++) {
        int cur = kt & 1;
        __syncthreads();
        if (kt < 3) { issue(kt + 1, cur ^ 1); cp_wait<1>(); }
        else        { cp_wait<0>(); }
        __syncthreads();

        uint32_t aB = aAddr0 + cur * A_CH_WORDS * 4;
        uint32_t bB = bAddr0 + cur * B_CH_WORDS * 4;
#pragma unroll
        for (int ks = 0; ks < 4; ks++) {
            int kw = ks * 8;
            uint32_t af[4][4], bf[4][2];
#pragma unroll
            for (int i = 0; i < 4; i++)
                ldsm_x4(af[i][0], af[i][1], af[i][2], af[i][3],
                        aB + (i * 16 * ROWW + kw) * 4);
#pragma unroll
            for (int jp = 0; jp < 2; jp++)
                ldsm_x4(bf[jp * 2][0], bf[jp * 2][1],
                        bf[jp * 2 + 1][0], bf[jp * 2 + 1][1],
                        bB + (jp * 16 * ROWW + kw) * 4);
#pragma unroll
            for (int i = 0; i < 4; i++)
#pragma unroll
                for (int j = 0; j < 4; j++)
                    mma_f16(acc[i][j], af[i][0], af[i][1], af[i][2], af[i][3],
                            bf[j][0], bf[j][1]);
        }
    }

    float normq = 0.17677669529663687f * LOG2E;  // 1/sqrt(32) * log2e
#pragma unroll
    for (int i = 0; i < 4; i++) {
#pragma unroll
        for (int j = 0; j < 4; j++) {
            int r0 = bM + warpM * 64 + i * 16 + gid;
            int c0 = bN + warpN * 32 + j * 8 + tid * 2;
#pragma unroll
            for (int e2 = 0; e2 < 2; e2++) {
                int row = r0 + e2 * 8;
                float v0 = acc[i][j][e2 * 2 + 0];
                float v1 = acc[i][j][e2 * 2 + 1];
                if (type == 4) {
                    out[row * 256 + c0]     = v0 + b_o[c0];
                    out[row * 256 + c0 + 1] = v1 + b_o[c0 + 1];
                } else {
                    if (type == 0) { v0 *= normq; v1 *= normq; }
                    if (type == 3) {
                        v0 = 1.f / (1.f + __expf(-(v0 + b_g[c0])));
                        v1 = 1.f / (1.f + __expf(-(v1 + b_g[c0 + 1])));
                    }
                    __half* Out = (type == 0) ? g_Qh : (type == 1) ? g_Kh
                                : (type == 2) ? g_Vh : g_Gh;
                    int s = row >> 8, rr = row & 255;
                    int h = c0 >> 5, d = c0 & 31;
                    *(__half2*)(Out + ((s * 8 + h) * 256 + rr) * 32 + d) =
                        __floats2half2_rn(v0, v1);
                }
            }
        }
    }
}

// ---------------------------------------------------------------------------
// Kernel 3: fp16 tensor-core attention with exp2 scores and rowsum-via-ones.
// V^T padded to 40 d-rows: row 32 = 1.0 (rowsum column), rows 33-39 = 0.
// ---------------------------------------------------------------------------
#define AT_KS_W 5120                 // 256 rows x 20 words
#define AT_VT_W (40 * 132)           // 5280 words
#define AT_PS_W 5120                 // 8 warps x 32 rows x 20 words
#define AT_SMEM_WORDS (AT_KS_W + AT_VT_W + AT_PS_W + 256)
#define ATTN_SMEM_BYTES (AT_SMEM_WORDS * 4)   // 63104

__global__ void __launch_bounds__(256, 2)
attn_mma_kernel(const float* __restrict__ bias_mask) {
    extern __shared__ uint32_t sm[];
    uint32_t* Ks = sm;                          // half[256][40]
    uint32_t* Vt = sm + AT_KS_W;                // half[40][264]
    uint32_t* Ps = sm + AT_KS_W + AT_VT_W;      // 8 x half[32][40]
    float*    Mb = (float*)(sm + AT_KS_W + AT_VT_W + AT_PS_W);  // [256]

    int s = blockIdx.x, h = blockIdx.y;
    int t = threadIdx.x, lane = t & 31, w = t >> 5;
    int gid = lane >> 2, tid = lane & 3;

    const __half* Qg = g_Qh + (s * 8 + h) * 8192;
    const __half* Kg = g_Kh + (s * 8 + h) * 8192;
    const __half* Vg = g_Vh + (s * 8 + h) * 8192;
    const __half* Gg = g_Gh + (s * 8 + h) * 8192;

    // ---- stage Q (raw half copy) into Ps region temporarily: [256][40]
    uint32_t* Qs = Ps;
#pragma unroll
    for (int i = t; i < 1024; i += 256) {
        uint4 raw = ((const uint4*)Qg)[i];
        int r = i >> 2, c = (i & 3) * 4;
        Qs[r * 20 + c + 0] = raw.x;
        Qs[r * 20 + c + 1] = raw.y;
        Qs[r * 20 + c + 2] = raw.z;
        Qs[r * 20 + c + 3] = raw.w;
    }
    __syncthreads();

    uint32_t qf[2][2][4];
#pragma unroll
    for (int i2 = 0; i2 < 2; i2++) {
        int r0 = w * 32 + i2 * 16;
#pragma unroll
        for (int ks = 0; ks < 2; ks++) {
            int kw = ks * 8;
            qf[i2][ks][0] = Qs[(r0 + gid) * 20 + kw + tid];
            qf[i2][ks][1] = Qs[(r0 + gid + 8) * 20 + kw + tid];
            qf[i2][ks][2] = Qs[(r0 + gid) * 20 + kw + tid + 4];
            qf[i2][ks][3] = Qs[(r0 + gid + 8) * 20 + kw + tid + 4];
        }
    }
    __syncthreads();

    // ---- stage K [key][d], V^T [d][key] (half), ones/zero pad rows, mask
    __half* VtH = (__half*)Vt;
#pragma unroll
    for (int i = t; i < 1024; i += 256) {
        int r = i >> 2, c = (i & 3) * 4;
        uint4 kraw = ((const uint4*)Kg)[i];
        Ks[r * 20 + c + 0] = kraw.x;
        Ks[r * 20 + c + 1] = kraw.y;
        Ks[r * 20 + c + 2] = kraw.z;
        Ks[r * 20 + c + 3] = kraw.w;
        uint4 vraw = ((const uint4*)Vg)[i];
        int d8 = (i & 3) * 8;
        const __half* vh = (const __half*)&vraw;
#pragma unroll
        for (int e = 0; e < 8; e++)
            VtH[(d8 + e) * 264 + r] = vh[e];
    }
    // pad rows 32..39: row 32 = 1.0 (rowsum), 33..39 = 0
    for (int i = t; i < 8 * 132; i += 256) {
        int dr = 32 + i / 132, c = i % 132;
        Vt[dr * 132 + c] = (dr == 32) ? 0x3C003C00u : 0u;
    }
    Mb[t] = (bias_mask[s * 256 + t] - 1.f) * (1e9f * LOG2E);
    __syncthreads();

    const float* biasBase = g_biasT + h * 65536;
    uint32_t* Pw = Ps + w * 640;

    float oacc[2][5][4];
#pragma unroll
    for (int i2 = 0; i2 < 2; i2++)
#pragma unroll
        for (int j2 = 0; j2 < 5; j2++)
#pragma unroll
            for (int e = 0; e < 4; e++) oacc[i2][j2][e] = 0.f;

    for (int kc = 0; kc < 256; kc += 32) {
        // ---- S chunk: [32 q x 32 k] via fp16 mma
        float sacc[2][4][4];
#pragma unroll
        for (int i2 = 0; i2 < 2; i2++)
#pragma unroll
            for (int j = 0; j < 4; j++)
#pragma unroll
                for (int e = 0; e < 4; e++) sacc[i2][j][e] = 0.f;

#pragma unroll
        for (int ks = 0; ks < 2; ks++) {
            int kw = ks * 8;
            uint32_t bf[4][2];
#pragma unroll
            for (int j = 0; j < 4; j++) {
                int n = kc + j * 8 + gid;
                bf[j][0] = Ks[n * 20 + kw + tid];
                bf[j][1] = Ks[n * 20 + kw + tid + 4];
            }
#pragma unroll
            for (int i2 = 0; i2 < 2; i2++)
#pragma unroll
                for (int j = 0; j < 4; j++)
                    mma_f16(sacc[i2][j], qf[i2][ks][0], qf[i2][ks][1],
                            qf[i2][ks][2], qf[i2][ks][3], bf[j][0], bf[j][1]);
        }

        // ---- hoisted mask values (shared across i2)
        float mreg[8];
#pragma unroll
        for (int j = 0; j < 4; j++) {
            int col = kc + j * 8 + tid * 2;
            mreg[j * 2 + 0] = Mb[col];
            mreg[j * 2 + 1] = Mb[col + 1];
        }

        // ---- bias + mask + exp2; P -> SMEM (half2); rowsum via ones-column
#pragma unroll
        for (int i2 = 0; i2 < 2; i2++) {
            int qrow = w * 32 + i2 * 16 + gid;
#pragma unroll
            for (int j = 0; j < 4; j++) {
                int col = kc + j * 8 + tid * 2;
                float2 b0 = *(const float2*)(biasBase + qrow * 256 + col);
                float2 b1 = *(const float2*)(biasBase + (qrow + 8) * 256 + col);
                float p0 = exp2f(sacc[i2][j][0] + b0.x + mreg[j * 2]);
                float p1 = exp2f(sacc[i2][j][1] + b0.y + mreg[j * 2 + 1]);
                float p2 = exp2f(sacc[i2][j][2] + b1.x + mreg[j * 2]);
                float p3 = exp2f(sacc[i2][j][3] + b1.y + mreg[j * 2 + 1]);
                int lr = i2 * 16 + gid;
                __half2 h01 = __floats2half2_rn(p0, p1);
                __half2 h23 = __floats2half2_rn(p2, p3);
                Pw[lr * 20 + 4 * j + tid]       = *(uint32_t*)&h01;
                Pw[(lr + 8) * 20 + 4 * j + tid] = *(uint32_t*)&h23;
            }
        }
        __syncwarp();

        // ---- O += P V (n = 40: 4 d-tiles + rowsum tile)
#pragma unroll
        for (int ks2 = 0; ks2 < 2; ks2++) {
            int kw = ks2 * 8;
            uint32_t pf[2][4];
#pragma unroll
            for (int i2 = 0; i2 < 2; i2++) {
                int lr = i2 * 16 + gid;
                pf[i2][0] = Pw[lr * 20 + kw + tid];
                pf[i2][1] = Pw[(lr + 8) * 20 + kw + tid];
                pf[i2][2] = Pw[lr * 20 + kw + tid + 4];
                pf[i2][3] = Pw[(lr + 8) * 20 + kw + tid + 4];
            }
            uint32_t vf[5][2];
#pragma unroll
            for (int j2 = 0; j2 < 5; j2++) {
                int d = j2 * 8 + gid;
                int kwd = (kc + ks2 * 16) >> 1;
                vf[j2][0] = Vt[d * 132 + kwd + tid];
                vf[j2][1] = Vt[d * 132 + kwd + tid + 4];
            }
#pragma unroll
            for (int i2 = 0; i2 < 2; i2++)
#pragma unroll
                for (int j2 = 0; j2 < 5; j2++)
                    mma_f16(oacc[i2][j2], pf[i2][0], pf[i2][1],
                            pf[i2][2], pf[i2][3], vf[j2][0], vf[j2][1]);
        }
        __syncwarp();
    }

    // ---- rowsum lives in column 32 (j2=4, tid==0 lanes); broadcast in quad
    float inv[2][2];
#pragma unroll
    for (int i2 = 0; i2 < 2; i2++) {
        float r0 = __shfl_sync(0xffffffffu, oacc[i2][4][0], lane & ~3);
        float r1 = __shfl_sync(0xffffffffu, oacc[i2][4][2], lane & ~3);
        inv[i2][0] = 1.f / r0;
        inv[i2][1] = 1.f / r1;
    }

    // ---- normalize, gate with G, write g_Oh = half(O * G)
    __half* Og = g_Oh + (s * 8 + h) * 8192;
#pragma unroll
    for (int i2 = 0; i2 < 2; i2++) {
        int r0 = w * 32 + i2 * 16 + gid;
#pragma unroll
        for (int j2 = 0; j2 < 4; j2++) {
            int c = j2 * 8 + tid * 2;
            float2 gv0 = __half22float2(*(const __half2*)(Gg + r0 * 32 + c));
            float2 gv1 = __half22float2(*(const __half2*)(Gg + (r0 + 8) * 32 + c));
            ((__half2*)(Og + r0 * 32 + c))[0] = __floats2half2_rn(
                oacc[i2][j2][0] * inv[i2][0] * gv0.x,
                oacc[i2][j2][1] * inv[i2][0] * gv0.y);
            ((__half2*)(Og + (r0 + 8) * 32 + c))[0] = __floats2half2_rn(
                oacc[i2][j2][2] * inv[i2][1] * gv1.x,
                oacc[i2][j2][3] * inv[i2][1] * gv1.y);
        }
    }
}

// ---------------------------------------------------------------------------
extern "C" void kernel_launch(void* const* d_in, const int* in_sizes, int n_in,
                              void* d_out, int out_size) {
    const float* q    = (const float*)d_in[0];
    const float* kv   = (const float*)d_in[1];
    const float* bias = (const float*)d_in[2];
    const float* mask = (const float*)d_in[3];
    const float* w_q  = (const float*)d_in[4];
    const float* w_k  = (const float*)d_in[5];
    const float* w_v  = (const float*)d_in[6];
    const float* w_g  = (const float*)d_in[7];
    const float* b_g  = (const float*)d_in[8];
    const float* w_o  = (const float*)d_in[9];
    const float* b_o  = (const float*)d_in[10];
    float* out = (float*)d_out;

    bias_transpose_kernel<<<(H_DIM * R_DIM * R_DIM + 255) / 256, 256>>>(bias);
    f2h_kernel<<<dim3(8192, 2), 256>>>(q, kv);
    wt_transpose_kernel<<<dim3(8, 8, 5), dim3(32, 8)>>>(w_q, w_k, w_v, w_g, w_o);

    cudaFuncSetAttribute(hgemm_kernel,
                         cudaFuncAttributeMaxDynamicSharedMemorySize,
                         GEMM_SMEM_BYTES);
    // projections: types 0..3
    hgemm_kernel<<<dim3(SR_DIM / 128, 2, 4), 256, GEMM_SMEM_BYTES>>>(
        b_g, b_o, out, 0);

    cudaFuncSetAttribute(attn_mma_kernel,
                         cudaFuncAttributeMaxDynamicSharedMemorySize,
                         ATTN_SMEM_BYTES);
    attn_mma_kernel<<<dim3(S_DIM, H_DIM), 256, ATTN_SMEM_BYTES>>>(mask);

    // output projection: type 4
    hgemm_kernel<<<dim3(SR_DIM / 128, 2, 1), 256, GEMM_SMEM_BYTES>>>(
        b_g, b_o, out, 4);
}

// round 17
// speedup vs baseline: 1.0572x; 1.0572x over previous
#include <cuda_runtime.h>
#include <cuda_fp16.h>
#include <math.h>
#include <stdint.h>

#define S_DIM 128
#define R_DIM 256
#define C_DIM 256
#define H_DIM 8
#define D_DIM 32
#define HD_DIM 256
#define SR_DIM (S_DIM * R_DIM)

#define LOG2E 1.4426950408889634f

// Scratch (device globals; allocation-free contract)
__device__ float  g_biasT[H_DIM * R_DIM * R_DIM];        // [h][q][k], pre-scaled by log2e
__device__ __half g_qh[SR_DIM * 256];                    // q input, half
__device__ __half g_kvh[SR_DIM * 256];                   // kv input, half
__device__ __half g_Qh[S_DIM * H_DIM * R_DIM * D_DIM];   // [s][h][r][d], pre-scaled norm*log2e
__device__ __half g_Kh[S_DIM * H_DIM * R_DIM * D_DIM];
__device__ __half g_Vh[S_DIM * H_DIM * R_DIM * D_DIM];
__device__ __half g_Gh[S_DIM * H_DIM * R_DIM * D_DIM];
__device__ __half g_Oh[S_DIM * H_DIM * R_DIM * D_DIM];   // gated O
__device__ __half g_WTh[5 * 256 * 256];                  // weights [n][k], half

// ---------------------------------------------------------------------------
// helpers
// ---------------------------------------------------------------------------
__device__ __forceinline__ void mma_f16(float c[4],
                                        uint32_t a0, uint32_t a1,
                                        uint32_t a2, uint32_t a3,
                                        uint32_t b0, uint32_t b1) {
    asm volatile(
        "mma.sync.aligned.m16n8k16.row.col.f32.f16.f16.f32 "
        "{%0,%1,%2,%3}, {%4,%5,%6,%7}, {%8,%9}, {%0,%1,%2,%3};"
        : "+f"(c[0]), "+f"(c[1]), "+f"(c[2]), "+f"(c[3])
        : "r"(a0), "r"(a1), "r"(a2), "r"(a3), "r"(b0), "r"(b1));
}

__device__ __forceinline__ void ldsm_x4(uint32_t& r0, uint32_t& r1,
                                        uint32_t& r2, uint32_t& r3,
                                        uint32_t addr) {
    asm volatile("ldmatrix.sync.aligned.m8n8.x4.shared.b16 {%0,%1,%2,%3}, [%4];"
                 : "=r"(r0), "=r"(r1), "=r"(r2), "=r"(r3) : "r"(addr));
}

__device__ __forceinline__ uint32_t ex2_h2(uint32_t x) {
    uint32_t d;
    asm("ex2.approx.f16x2 %0, %1;" : "=r"(d) : "r"(x));
    return d;
}

__device__ __forceinline__ void cp16(uint32_t smem_addr, const void* gptr) {
    asm volatile("cp.async.cg.shared.global [%0], [%1], 16;"
                 :: "r"(smem_addr), "l"(gptr));
}
__device__ __forceinline__ void cp_commit() {
    asm volatile("cp.async.commit_group;");
}
template <int N>
__device__ __forceinline__ void cp_wait() {
    asm volatile("cp.async.wait_group %0;" :: "n"(N));
}

// fp16 GEMM tiling (unchanged): block 128x128, BK=64, 8 warps of 64x32,
// ldmatrix frag loads, 2-stage pipeline, 2 CTAs/SM.
#define ROWW 36
#define A_CH_WORDS (128 * ROWW)
#define B_CH_WORDS (128 * ROWW)
#define GEMM_SMEM_BYTES (2 * (A_CH_WORDS + B_CH_WORDS) * 4)  // 73728

// ---------------------------------------------------------------------------
// Kernel 1: bias [q][k][h] -> biasT [h][q][k], scaled by log2e.
// ---------------------------------------------------------------------------
__global__ void bias_transpose_kernel(const float* __restrict__ bias) {
    int idx = blockIdx.x * blockDim.x + threadIdx.x;
    if (idx < H_DIM * R_DIM * R_DIM) {
        int k  = idx & 255;
        int qq = (idx >> 8) & 255;
        int h  = idx >> 16;
        g_biasT[idx] = bias[((qq << 8) + k) * 8 + h] * LOG2E;
    }
}

// ---------------------------------------------------------------------------
// Kernel 1b: fp32 -> fp16 conversion of the two activation inputs.
// ---------------------------------------------------------------------------
__global__ void f2h_kernel(const float* __restrict__ qin,
                           const float* __restrict__ kvin) {
    const float* src = blockIdx.y ? kvin : qin;
    __half* dst = blockIdx.y ? g_kvh : g_qh;
    int i = blockIdx.x * 256 + threadIdx.x;     // float4 index
    float4 v = ((const float4*)src)[i];
    __half2* d = (__half2*)(dst + i * 4);
    d[0] = __floats2half2_rn(v.x, v.y);
    d[1] = __floats2half2_rn(v.z, v.w);
}

// ---------------------------------------------------------------------------
// Kernel 1c: transpose five 256x256 weight matrices to K-major [n][k], half.
// ---------------------------------------------------------------------------
__global__ void wt_transpose_kernel(const float* __restrict__ w_q,
                                    const float* __restrict__ w_k,
                                    const float* __restrict__ w_v,
                                    const float* __restrict__ w_g,
                                    const float* __restrict__ w_o) {
    __shared__ float tile[32][33];
    int which = blockIdx.z;
    const float* W = (which == 0) ? w_q : (which == 1) ? w_k
                   : (which == 2) ? w_v : (which == 3) ? w_g : w_o;
    __half* Out = g_WTh + which * 65536;
    int bx = blockIdx.x * 32, by = blockIdx.y * 32;
    int tx = threadIdx.x, ty = threadIdx.y;   // 32 x 8
#pragma unroll
    for (int i = 0; i < 32; i += 8)
        tile[ty + i][tx] = W[(by + ty + i) * 256 + bx + tx];
    __syncthreads();
#pragma unroll
    for (int i = 0; i < 32; i += 8)
        Out[(bx + ty + i) * 256 + by + tx] = __float2half_rn(tile[tx][ty + i]);
}

// ---------------------------------------------------------------------------
// Kernel 2: fp16 m16n8k16 GEMM with ldmatrix fragment loads (unchanged).
// type 0: Q (scaled norm*log2e), 1: K, 2: V, 3: G (sigmoid), 4: outproj.
// ---------------------------------------------------------------------------
__global__ void __launch_bounds__(256, 2)
hgemm_kernel(const float* __restrict__ b_g,
             const float* __restrict__ b_o,
             float* __restrict__ out,
             int type_base) {
    extern __shared__ uint32_t smem[];
    uint32_t* Asm = smem;
    uint32_t* Bsm = smem + 2 * A_CH_WORDS;

    int type = blockIdx.z + type_base;
    const __half* Ah = (type == 1 || type == 2) ? g_kvh
                     : (type == 4) ? g_Oh : g_qh;
    const __half* Bh = g_WTh + type * 65536;

    int t = threadIdx.x, lane = t & 31, w = t >> 5;
    int warpM = w >> 2, warpN = w & 3;
    int bM = blockIdx.x * 128;
    int bN = blockIdx.y * 128;
    int gid = lane >> 2, tid = lane & 3;

    uint32_t asBase = (uint32_t)__cvta_generic_to_shared(Asm);
    uint32_t bsBase = (uint32_t)__cvta_generic_to_shared(Bsm);

    int a_row = warpM * 64 + (lane & 7) + ((lane >> 3) & 1) * 8;
    int a_colw = (lane >> 4) * 4;
    int b_row = warpN * 32 + (lane & 7) + (lane >> 4) * 8;
    int b_colw = ((lane >> 3) & 1) * 4;
    uint32_t aAddr0 = asBase + (a_row * ROWW + a_colw) * 4;
    uint32_t bAddr0 = bsBase + (b_row * ROWW + b_colw) * 4;

    auto issue = [&](int kt, int buf) {
        int kc = kt * 64;
#pragma unroll
        for (int p = 0; p < 4; p++) {
            int idx = t + p * 256;
            int r = idx >> 3, c4 = idx & 7;
            const __half* src;
            if (type == 4) {
                int m = bM + r;
                int s = m >> 8, rr = m & 255;
                int head = (kc >> 5) + (c4 >> 2);
                int d0 = (c4 & 3) * 8;
                src = g_Oh + ((s * 8 + head) * 256 + rr) * 32 + d0;
            } else {
                src = Ah + (bM + r) * 256 + kc + c4 * 8;
            }
            cp16(asBase + (buf * A_CH_WORDS + r * ROWW + c4 * 4) * 4, src);
        }
#pragma unroll
        for (int p = 0; p < 4; p++) {
            int idx = t + p * 256;
            int r = idx >> 3, c4 = idx & 7;
            cp16(bsBase + (buf * B_CH_WORDS + r * ROWW + c4 * 4) * 4,
                 Bh + (bN + r) * 256 + kc + c4 * 8);
        }
        cp_commit();
    };

    float acc[4][4][4];
#pragma unroll
    for (int i = 0; i < 4; i++)
#pragma unroll
        for (int j = 0; j < 4; j++)
#pragma unroll
            for (int r = 0; r < 4; r++) acc[i][j][r] = 0.f;

    issue(0, 0);

    for (int kt = 0; kt < 4; kt++) {
        int cur = kt & 1;
        __syncthreads();
        if (kt < 3) { issue(kt + 1, cur ^ 1); cp_wait<1>(); }
        else        { cp_wait<0>(); }
        __syncthreads();

        uint32_t aB = aAddr0 + cur * A_CH_WORDS * 4;
        uint32_t bB = bAddr0 + cur * B_CH_WORDS * 4;
#pragma unroll
        for (int ks = 0; ks < 4; ks++) {
            int kw = ks * 8;
            uint32_t af[4][4], bf[4][2];
#pragma unroll
            for (int i = 0; i < 4; i++)
                ldsm_x4(af[i][0], af[i][1], af[i][2], af[i][3],
                        aB + (i * 16 * ROWW + kw) * 4);
#pragma unroll
            for (int jp = 0; jp < 2; jp++)
                ldsm_x4(bf[jp * 2][0], bf[jp * 2][1],
                        bf[jp * 2 + 1][0], bf[jp * 2 + 1][1],
                        bB + (jp * 16 * ROWW + kw) * 4);
#pragma unroll
            for (int i = 0; i < 4; i++)
#pragma unroll
                for (int j = 0; j < 4; j++)
                    mma_f16(acc[i][j], af[i][0], af[i][1], af[i][2], af[i][3],
                            bf[j][0], bf[j][1]);
        }
    }

    float normq = 0.17677669529663687f * LOG2E;  // 1/sqrt(32) * log2e
#pragma unroll
    for (int i = 0; i < 4; i++) {
#pragma unroll
        for (int j = 0; j < 4; j++) {
            int r0 = bM + warpM * 64 + i * 16 + gid;
            int c0 = bN + warpN * 32 + j * 8 + tid * 2;
#pragma unroll
            for (int e2 = 0; e2 < 2; e2++) {
                int row = r0 + e2 * 8;
                float v0 = acc[i][j][e2 * 2 + 0];
                float v1 = acc[i][j][e2 * 2 + 1];
                if (type == 4) {
                    out[row * 256 + c0]     = v0 + b_o[c0];
                    out[row * 256 + c0 + 1] = v1 + b_o[c0 + 1];
                } else {
                    if (type == 0) { v0 *= normq; v1 *= normq; }
                    if (type == 3) {
                        v0 = 1.f / (1.f + __expf(-(v0 + b_g[c0])));
                        v1 = 1.f / (1.f + __expf(-(v1 + b_g[c0 + 1])));
                    }
                    __half* Out = (type == 0) ? g_Qh : (type == 1) ? g_Kh
                                : (type == 2) ? g_Vh : g_Gh;
                    int s = row >> 8, rr = row & 255;
                    int h = c0 >> 5, d = c0 & 31;
                    *(__half2*)(Out + ((s * 8 + h) * 256 + rr) * 32 + d) =
                        __floats2half2_rn(v0, v1);
                }
            }
        }
    }
}

// ---------------------------------------------------------------------------
// Kernel 3: fp16 attention, FA2-style: P stays in registers (S C-frags pack
// directly into PV A-frags).  No P SMEM, no syncwarp in the main loop.
// exp via ex2.approx.f16x2 on packed half2.  Rowsum via ones-column (d=32).
// SMEM: Ks (Q staging, then K) + Vt + Mb = 42.6 KB -> 2 CTAs/SM.
// ---------------------------------------------------------------------------
#define AT_KS_W 5120                 // 256 rows x 20 words
#define AT_VT_W (40 * 132)           // 5280 words
#define AT_SMEM_WORDS (AT_KS_W + AT_VT_W + 256)
#define ATTN_SMEM_BYTES (AT_SMEM_WORDS * 4)   // 42624

__global__ void __launch_bounds__(256, 2)
attn_mma_kernel(const float* __restrict__ bias_mask) {
    extern __shared__ uint32_t sm[];
    uint32_t* Ks = sm;                          // half[256][40]: Q staging, then K
    uint32_t* Vt = sm + AT_KS_W;                // half[40][264]
    float*    Mb = (float*)(sm + AT_KS_W + AT_VT_W);  // [256]

    int s = blockIdx.x, h = blockIdx.y;
    int t = threadIdx.x, lane = t & 31, w = t >> 5;
    int gid = lane >> 2, tid = lane & 3;

    const __half* Qg = g_Qh + (s * 8 + h) * 8192;
    const __half* Kg = g_Kh + (s * 8 + h) * 8192;
    const __half* Vg = g_Vh + (s * 8 + h) * 8192;
    const __half* Gg = g_Gh + (s * 8 + h) * 8192;

    // ---- phase 1: stage Q -> Ks region, V -> Vt (transposed), mask
    __half* VtH = (__half*)Vt;
#pragma unroll
    for (int i = t; i < 1024; i += 256) {
        uint4 raw = ((const uint4*)Qg)[i];
        int r = i >> 2, c = (i & 3) * 4;
        Ks[r * 20 + c + 0] = raw.x;
        Ks[r * 20 + c + 1] = raw.y;
        Ks[r * 20 + c + 2] = raw.z;
        Ks[r * 20 + c + 3] = raw.w;
        uint4 vraw = ((const uint4*)Vg)[i];
        int d8 = (i & 3) * 8;
        const __half* vh = (const __half*)&vraw;
#pragma unroll
        for (int e = 0; e < 8; e++)
            VtH[(d8 + e) * 264 + r] = vh[e];
    }
    // pad Vt rows 32..39: row 32 = 1.0 (rowsum), 33..39 = 0
    for (int i = t; i < 8 * 132; i += 256) {
        int dr = 32 + i / 132, c = i % 132;
        Vt[dr * 132 + c] = (dr == 32) ? 0x3C003C00u : 0u;
    }
    Mb[t] = (bias_mask[s * 256 + t] - 1.f) * (1e9f * LOG2E);
    __syncthreads();

    // ---- extract Q fragments (register resident)
    uint32_t qf[2][2][4];
#pragma unroll
    for (int i2 = 0; i2 < 2; i2++) {
        int r0 = w * 32 + i2 * 16;
#pragma unroll
        for (int ks = 0; ks < 2; ks++) {
            int kw = ks * 8;
            qf[i2][ks][0] = Ks[(r0 + gid) * 20 + kw + tid];
            qf[i2][ks][1] = Ks[(r0 + gid + 8) * 20 + kw + tid];
            qf[i2][ks][2] = Ks[(r0 + gid) * 20 + kw + tid + 4];
            qf[i2][ks][3] = Ks[(r0 + gid + 8) * 20 + kw + tid + 4];
        }
    }
    __syncthreads();

    // ---- phase 2: stage K over the Q region
#pragma unroll
    for (int i = t; i < 1024; i += 256) {
        uint4 kraw = ((const uint4*)Kg)[i];
        int r = i >> 2, c = (i & 3) * 4;
        Ks[r * 20 + c + 0] = kraw.x;
        Ks[r * 20 + c + 1] = kraw.y;
        Ks[r * 20 + c + 2] = kraw.z;
        Ks[r * 20 + c + 3] = kraw.w;
    }
    __syncthreads();

    const float* biasBase = g_biasT + h * 65536;

    float oacc[2][5][4];
#pragma unroll
    for (int i2 = 0; i2 < 2; i2++)
#pragma unroll
        for (int j2 = 0; j2 < 5; j2++)
#pragma unroll
            for (int e = 0; e < 4; e++) oacc[i2][j2][e] = 0.f;

    for (int kc = 0; kc < 256; kc += 32) {
        // ---- S chunk: [32 q x 32 k] via fp16 mma
        float sacc[2][4][4];
#pragma unroll
        for (int i2 = 0; i2 < 2; i2++)
#pragma unroll
            for (int j = 0; j < 4; j++)
#pragma unroll
                for (int e = 0; e < 4; e++) sacc[i2][j][e] = 0.f;

#pragma unroll
        for (int ks = 0; ks < 2; ks++) {
            int kw = ks * 8;
            uint32_t bf[4][2];
#pragma unroll
            for (int j = 0; j < 4; j++) {
                int n = kc + j * 8 + gid;
                bf[j][0] = Ks[n * 20 + kw + tid];
                bf[j][1] = Ks[n * 20 + kw + tid + 4];
            }
#pragma unroll
            for (int i2 = 0; i2 < 2; i2++)
#pragma unroll
                for (int j = 0; j < 4; j++)
                    mma_f16(sacc[i2][j], qf[i2][ks][0], qf[i2][ks][1],
                            qf[i2][ks][2], qf[i2][ks][3], bf[j][0], bf[j][1]);
        }

        // ---- hoisted mask values
        float mreg[8];
#pragma unroll
        for (int j = 0; j < 4; j++) {
            int col = kc + j * 8 + tid * 2;
            mreg[j * 2 + 0] = Mb[col];
            mreg[j * 2 + 1] = Mb[col + 1];
        }

        // ---- bias + mask, pack to half2, exp2 in f16x2 -> PV A-frags (regs)
        uint32_t paf[2][2][4];
#pragma unroll
        for (int i2 = 0; i2 < 2; i2++) {
            int qrow = w * 32 + i2 * 16 + gid;
#pragma unroll
            for (int j = 0; j < 4; j++) {
                int col = kc + j * 8 + tid * 2;
                float2 b0 = *(const float2*)(biasBase + qrow * 256 + col);
                float2 b1 = *(const float2*)(biasBase + (qrow + 8) * 256 + col);
                float f0 = sacc[i2][j][0] + b0.x + mreg[j * 2];
                float f1 = sacc[i2][j][1] + b0.y + mreg[j * 2 + 1];
                float f2 = sacc[i2][j][2] + b1.x + mreg[j * 2];
                float f3 = sacc[i2][j][3] + b1.y + mreg[j * 2 + 1];
                __half2 x01 = __floats2half2_rn(f0, f1);
                __half2 x23 = __floats2half2_rn(f2, f3);
                paf[i2][j >> 1][(j & 1) * 2 + 0] = ex2_h2(*(uint32_t*)&x01);
                paf[i2][j >> 1][(j & 1) * 2 + 1] = ex2_h2(*(uint32_t*)&x23);
            }
        }

        // ---- O += P V directly from register fragments (n = 40 incl rowsum)
#pragma unroll
        for (int ks2 = 0; ks2 < 2; ks2++) {
            uint32_t vf[5][2];
#pragma unroll
            for (int j2 = 0; j2 < 5; j2++) {
                int d = j2 * 8 + gid;
                int kwd = (kc + ks2 * 16) >> 1;
                vf[j2][0] = Vt[d * 132 + kwd + tid];
                vf[j2][1] = Vt[d * 132 + kwd + tid + 4];
            }
#pragma unroll
            for (int i2 = 0; i2 < 2; i2++)
#pragma unroll
                for (int j2 = 0; j2 < 5; j2++)
                    mma_f16(oacc[i2][j2], paf[i2][ks2][0], paf[i2][ks2][1],
                            paf[i2][ks2][2], paf[i2][ks2][3],
                            vf[j2][0], vf[j2][1]);
        }
    }

    // ---- rowsum in column 32 (j2=4, tid==0, c0/c2); broadcast within quad
    float inv[2][2];
#pragma unroll
    for (int i2 = 0; i2 < 2; i2++) {
        float r0 = __shfl_sync(0xffffffffu, oacc[i2][4][0], lane & ~3);
        float r1 = __shfl_sync(0xffffffffu, oacc[i2][4][2], lane & ~3);
        inv[i2][0] = 1.f / r0;
        inv[i2][1] = 1.f / r1;
    }

    // ---- normalize, gate with G, write g_Oh = half(O * G)
    __half* Og = g_Oh + (s * 8 + h) * 8192;
#pragma unroll
    for (int i2 = 0; i2 < 2; i2++) {
        int r0 = w * 32 + i2 * 16 + gid;
#pragma unroll
        for (int j2 = 0; j2 < 4; j2++) {
            int c = j2 * 8 + tid * 2;
            float2 gv0 = __half22float2(*(const __half2*)(Gg + r0 * 32 + c));
            float2 gv1 = __half22float2(*(const __half2*)(Gg + (r0 + 8) * 32 + c));
            ((__half2*)(Og + r0 * 32 + c))[0] = __floats2half2_rn(
                oacc[i2][j2][0] * inv[i2][0] * gv0.x,
                oacc[i2][j2][1] * inv[i2][0] * gv0.y);
            ((__half2*)(Og + (r0 + 8) * 32 + c))[0] = __floats2half2_rn(
                oacc[i2][j2][2] * inv[i2][1] * gv1.x,
                oacc[i2][j2][3] * inv[i2][1] * gv1.y);
        }
    }
}

// ---------------------------------------------------------------------------
extern "C" void kernel_launch(void* const* d_in, const int* in_sizes, int n_in,
                              void* d_out, int out_size) {
    const float* q    = (const float*)d_in[0];
    const float* kv   = (const float*)d_in[1];
    const float* bias = (const float*)d_in[2];
    const float* mask = (const float*)d_in[3];
    const float* w_q  = (const float*)d_in[4];
    const float* w_k  = (const float*)d_in[5];
    const float* w_v  = (const float*)d_in[6];
    const float* w_g  = (const float*)d_in[7];
    const float* b_g  = (const float*)d_in[8];
    const float* w_o  = (const float*)d_in[9];
    const float* b_o  = (const float*)d_in[10];
    float* out = (float*)d_out;

    bias_transpose_kernel<<<(H_DIM * R_DIM * R_DIM + 255) / 256, 256>>>(bias);
    f2h_kernel<<<dim3(8192, 2), 256>>>(q, kv);
    wt_transpose_kernel<<<dim3(8, 8, 5), dim3(32, 8)>>>(w_q, w_k, w_v, w_g, w_o);

    cudaFuncSetAttribute(hgemm_kernel,
                         cudaFuncAttributeMaxDynamicSharedMemorySize,
                         GEMM_SMEM_BYTES);
    // projections: types 0..3
    hgemm_kernel<<<dim3(SR_DIM / 128, 2, 4), 256, GEMM_SMEM_BYTES>>>(
        b_g, b_o, out, 0);

    cudaFuncSetAttribute(attn_mma_kernel,
                         cudaFuncAttributeMaxDynamicSharedMemorySize,
                         ATTN_SMEM_BYTES);
    attn_mma_kernel<<<dim3(S_DIM, H_DIM), 256, ATTN_SMEM_BYTES>>>(mask);

    // output projection: type 4
    hgemm_kernel<<<dim3(SR_DIM / 128, 2, 1), 256, GEMM_SMEM_BYTES>>>(
        b_g, b_o, out, 4);
}